// round 2
// baseline (speedup 1.0000x reference)
#include <cuda_runtime.h>
#include <math.h>

// ---------------------------------------------------------------------------
// ResidualSieveKAN — 6-layer KAN on GB300.
// Spline path exploits uniform knots: only 4 nonzero cubic B-spline bases per
// (sample, feature). Per layer: y[b,o] = ws * sum_i sum_t c_t(b,i) * sw[o,i,m(b,i)+t]
//                                 (+ wb * silu-GEMM, skipped when wb==0)
//                                 (+ residual when in==out).
// ---------------------------------------------------------------------------

#define BM       64     // batch rows per CTA
#define BN       64     // output cols per CTA
#define XS       65     // xT smem row stride (bank-conflict free)
#define WSD      105    // swS smem row stride (odd -> conflict-free lane reads)
#define NBASIS   103
#define NTHREADS 256

__device__ float g_buf0[2048 * 243];
__device__ float g_buf1[2048 * 243];

// Stage coefficients (4 blending weights + packed clamped row indices) and the
// weight slab sw[o0:o0+BN, i, :] into shared memory buffers.
__device__ __forceinline__ void stage_tile(
    const float* __restrict__ xT,
    float* __restrict__ swS_buf,
    float4* __restrict__ c4_buf,
    int* __restrict__ mA_buf,
    const float* __restrict__ sw,
    int i, int in_f, int o0, int ow, int tid)
{
    if (tid < BM) {
        float x  = xT[i * XS + tid];
        float p  = (x + 0.5f) * 50.0f;          // (x - grid0_interior)/H, H = 0.02
        float mf = floorf(p);
        int   m  = (int)mf;
        float u  = p - mf;
        float u2 = u * u, u3 = u2 * u;
        float om = 1.0f - u;
        float c0 = om * om * om * (1.0f / 6.0f);
        float c1 = (3.0f * u3 - 6.0f * u2 + 4.0f) * (1.0f / 6.0f);
        float c2 = (-3.0f * u3 + 3.0f * u2 + 3.0f * u + 1.0f) * (1.0f / 6.0f);
        float c3 = u3 * (1.0f / 6.0f);
        if (m < -3 || m > 102) {                 // outside grid support entirely
            c0 = c1 = c2 = c3 = 0.0f; m = 0;
        } else {                                  // margin: drop out-of-array bases
            if (m     < 0 || m     > 102) c0 = 0.0f;
            if (m + 1 < 0 || m + 1 > 102) c1 = 0.0f;
            if (m + 2 < 0 || m + 2 > 102) c2 = 0.0f;
            if (m + 3 < 0 || m + 3 > 102) c3 = 0.0f;
        }
        int n0 = min(max(m,     0), 102);
        int n1 = min(max(m + 1, 0), 102);
        int n2 = min(max(m + 2, 0), 102);
        int n3 = min(max(m + 3, 0), 102);
        c4_buf[tid] = make_float4(c0, c1, c2, c3);
        mA_buf[tid] = n0 | (n1 << 8) | (n2 << 16) | (n3 << 24);
    }

    // Weight slab: 64 o-rows x 103 n-values. Quarter-warp per o-row:
    // coalesced LDG over n, conflict-free-ish STS into [o][105] layout.
    int o  = tid >> 2;
    int nb = (tid & 3) * 26;
    int og = min(o, ow - 1);
    const float* src = sw + ((size_t)(o0 + og) * in_f + i) * NBASIS + nb;
    float*       dst = swS_buf + o * WSD + nb;
#pragma unroll
    for (int k = 0; k < 26; k++) {
        if (nb + k < NBASIS) dst[k] = src[k];
    }
}

__global__ void __launch_bounds__(NTHREADS, 1)
kan_layer_kernel(const float* __restrict__ xin, float* __restrict__ dfinal,
                 int src_sel, int dst_sel,
                 const float* __restrict__ sw, const float* __restrict__ bw,
                 const float* __restrict__ wbp, const float* __restrict__ wsp,
                 int in_f, int out_f, int residual)
{
    const float* hin  = (src_sel == 0) ? xin : (src_sel == 1 ? g_buf0 : g_buf1);
    float*       hout = (dst_sel == 1) ? g_buf0 : (dst_sel == 2 ? g_buf1 : dfinal);

    extern __shared__ float smem[];
    // layout: c4 (16B aligned) | mA | xT | swS(double buffered)
    float4* c4  = (float4*)smem;                       // [2][BM]
    int*    mA  = (int*)(c4 + 2 * BM);                 // [2][BM]
    float*  xT  = (float*)(mA + 2 * BM);               // [in_f][XS]
    float*  swS = xT + (size_t)in_f * XS;              // [2][BN][WSD]

    const int tid = threadIdx.x;
    const int b0  = blockIdx.x * BM;
    const int o0  = blockIdx.y * BN;
    const int ow  = min(BN, out_f - o0);

    // Load x tile transposed into smem: xT[i][b_local].
    for (int idx = tid; idx < BM * in_f; idx += NTHREADS) {
        int b = idx / in_f;
        int i = idx - b * in_f;
        xT[i * XS + b] = hin[(size_t)(b0 + b) * in_f + i];
    }
    __syncthreads();

    const int w     = tid >> 5;
    const int l     = tid & 31;
    const int bbase = w * 8;

    float acc0[8], acc1[8];
#pragma unroll
    for (int r = 0; r < 8; r++) { acc0[r] = 0.0f; acc1[r] = 0.0f; }

    const float* rowA0 = swS + l * WSD;            // buffer 0, o = l
    const float* rowB0 = swS + (l + 32) * WSD;     // buffer 0, o = l+32

    // Prologue: stage i = 0 into buffer 0.
    stage_tile(xT, swS, c4, mA, sw, 0, in_f, o0, ow, tid);
    __syncthreads();

    for (int i = 0; i < in_f; i++) {
        const int cur = i & 1;
        if (i + 1 < in_f)
            stage_tile(xT, swS + (cur ^ 1) * (BN * WSD), c4 + (cur ^ 1) * BM,
                       mA + (cur ^ 1) * BM, sw, i + 1, in_f, o0, ow, tid);

        const float*  rowA = rowA0 + cur * (BN * WSD);
        const float*  rowB = rowB0 + cur * (BN * WSD);
        const float4* C    = c4 + cur * BM;
        const int*    M    = mA + cur * BM;

#pragma unroll
        for (int r = 0; r < 8; r++) {
            float4 c  = C[bbase + r];
            int    pk = M[bbase + r];
            int n0 =  pk        & 255;
            int n1 = (pk >> 8)  & 255;
            int n2 = (pk >> 16) & 255;
            int n3 = (pk >> 24) & 255;
            float a = acc0[r];
            a = fmaf(c.x, rowA[n0], a);
            a = fmaf(c.y, rowA[n1], a);
            a = fmaf(c.z, rowA[n2], a);
            a = fmaf(c.w, rowA[n3], a);
            acc0[r] = a;
            float bacc = acc1[r];
            bacc = fmaf(c.x, rowB[n0], bacc);
            bacc = fmaf(c.y, rowB[n1], bacc);
            bacc = fmaf(c.z, rowB[n2], bacc);
            bacc = fmaf(c.w, rowB[n3], bacc);
            acc1[r] = bacc;
        }
        __syncthreads();
    }

    const float wsv = wsp[0];
    const float wbv = wbp[0];

    // Base (silu @ bw^T) path — dataset has wb == 0, so this is normally skipped.
    float baseA[8], baseB[8];
#pragma unroll
    for (int r = 0; r < 8; r++) { baseA[r] = 0.0f; baseB[r] = 0.0f; }
    if (wbv != 0.0f) {
        for (int i = 0; i < in_f; i++) {
            float bwA = (l < ow)      ? bw[(size_t)(o0 + l) * in_f + i]      : 0.0f;
            float bwB = (l + 32 < ow) ? bw[(size_t)(o0 + l + 32) * in_f + i] : 0.0f;
#pragma unroll
            for (int r = 0; r < 8; r++) {
                float xv = xT[i * XS + bbase + r];
                float s  = xv / (1.0f + expf(-xv));
                baseA[r] = fmaf(s, bwA, baseA[r]);
                baseB[r] = fmaf(s, bwB, baseB[r]);
            }
        }
    }

#pragma unroll
    for (int r = 0; r < 8; r++) {
        int b = b0 + bbase + r;
        if (l < ow) {
            float v = wsv * acc0[r] + wbv * baseA[r];
            if (residual) v += xT[(o0 + l) * XS + bbase + r];
            hout[(size_t)b * out_f + o0 + l] = v;
        }
        if (l + 32 < ow) {
            float v = wsv * acc1[r] + wbv * baseB[r];
            if (residual) v += xT[(o0 + l + 32) * XS + bbase + r];
            hout[(size_t)b * out_f + o0 + l + 32] = v;
        }
    }
}

// Final layer: 243 -> 1. One thread per batch row.
__global__ void __launch_bounds__(256)
kan_last_kernel(int src_sel,
                const float* __restrict__ sw, const float* __restrict__ bw,
                const float* __restrict__ wbp, const float* __restrict__ wsp,
                float* __restrict__ out, int in_f)
{
    const float* hin = (src_sel == 1) ? g_buf0 : g_buf1;
    int b = blockIdx.x * blockDim.x + threadIdx.x;
    if (b >= 2048) return;

    const float wbv = wbp[0];
    float accS = 0.0f, accB = 0.0f;
    for (int i = 0; i < in_f; i++) {
        float x  = hin[(size_t)b * in_f + i];
        float p  = (x + 0.5f) * 50.0f;
        float mf = floorf(p);
        int   m  = (int)mf;
        float u  = p - mf;
        float u2 = u * u, u3 = u2 * u;
        float om = 1.0f - u;
        float c0 = om * om * om * (1.0f / 6.0f);
        float c1 = (3.0f * u3 - 6.0f * u2 + 4.0f) * (1.0f / 6.0f);
        float c2 = (-3.0f * u3 + 3.0f * u2 + 3.0f * u + 1.0f) * (1.0f / 6.0f);
        float c3 = u3 * (1.0f / 6.0f);
        if (m < -3 || m > 102) { c0 = c1 = c2 = c3 = 0.0f; m = 0; }
        else {
            if (m     < 0 || m     > 102) c0 = 0.0f;
            if (m + 1 < 0 || m + 1 > 102) c1 = 0.0f;
            if (m + 2 < 0 || m + 2 > 102) c2 = 0.0f;
            if (m + 3 < 0 || m + 3 > 102) c3 = 0.0f;
        }
        int n0 = min(max(m,     0), 102);
        int n1 = min(max(m + 1, 0), 102);
        int n2 = min(max(m + 2, 0), 102);
        int n3 = min(max(m + 3, 0), 102);
        const float* row = sw + (size_t)i * NBASIS;
        accS = fmaf(c0, row[n0], accS);
        accS = fmaf(c1, row[n1], accS);
        accS = fmaf(c2, row[n2], accS);
        accS = fmaf(c3, row[n3], accS);
        if (wbv != 0.0f) accB = fmaf(x / (1.0f + expf(-x)), bw[i], accB);
    }
    out[b] = wsp[0] * accS + wbv * accB;
}

extern "C" void kernel_launch(void* const* d_in, const int* in_sizes, int n_in,
                              void* d_out, int out_size)
{
    const float* x = (const float*)d_in[0];
    const float* bw[6]; const float* sw[6]; const float* wb[6]; const float* ws[6];
    for (int layer = 0; layer < 6; layer++) {
        bw[layer] = (const float*)d_in[1 + 4 * layer];
        sw[layer] = (const float*)d_in[2 + 4 * layer];
        wb[layer] = (const float*)d_in[3 + 4 * layer];
        ws[layer] = (const float*)d_in[4 + 4 * layer];
    }
    float* out = (float*)d_out;

    // smem bytes: c4 (2*BM float4) + mA (2*BM int) + xT (in_f*XS) + swS (2*BN*WSD)
    size_t fixed   = (size_t)(2 * BM * 4 + 2 * BM + 2 * BN * WSD) * 4;
    size_t smem64  = fixed + (size_t)64  * XS * 4;
    size_t smem243 = fixed + (size_t)243 * XS * 4;

    cudaFuncSetAttribute(kan_layer_kernel,
                         cudaFuncAttributeMaxDynamicSharedMemorySize,
                         (int)smem243);

    dim3 grid(2048 / BM, (243 + BN - 1) / BN);
    dim3 blk(NTHREADS);

    kan_layer_kernel<<<grid, blk, smem64 >>>(x, out, 0, 1, sw[0], bw[0], wb[0], ws[0],  64, 243, 0);
    kan_layer_kernel<<<grid, blk, smem243>>>(x, out, 1, 2, sw[1], bw[1], wb[1], ws[1], 243, 243, 1);
    kan_layer_kernel<<<grid, blk, smem243>>>(x, out, 2, 1, sw[2], bw[2], wb[2], ws[2], 243, 243, 1);
    kan_layer_kernel<<<grid, blk, smem243>>>(x, out, 1, 2, sw[3], bw[3], wb[3], ws[3], 243, 243, 1);
    kan_layer_kernel<<<grid, blk, smem243>>>(x, out, 2, 1, sw[4], bw[4], wb[4], ws[4], 243, 243, 1);
    kan_last_kernel<<<2048 / 256, 256>>>(1, sw[5], bw[5], wb[5], ws[5], out, 243);
}

// round 3
// speedup vs baseline: 1.2294x; 1.2294x over previous
#include <cuda_runtime.h>
#include <math.h>

// ---------------------------------------------------------------------------
// ResidualSieveKAN — 6-layer KAN on GB300, v2.
// Uniform knots => 4 nonzero cubic B-spline bases per (sample, feature).
//   y[b,o] = ws * sum_i sum_t c_t(b,i) * sw[o,i,m(b,i)+t]  (+ residual)
// v2: weights repacked once per launch to [i][o(pad 256)][105] so the per-i
// slab is one contiguous, 16B-aligned block (float4 memcpy staging);
// coefficients precomputed per layer into global scratch; 128x32 tiles,
// 512 threads, double-buffered smem.
// ---------------------------------------------------------------------------

#define NBASIS 103
#define WSD    105     // odd row stride: compute LDS banks (9*l+n)%32 all distinct
#define OPAD   256
#define BM     128
#define BN     32
#define LTH    512

__device__ float  g_wp0[(size_t)64 * OPAD * WSD];
__device__ float  g_wpm[(size_t)4 * 243 * OPAD * WSD];
__device__ float  g_buf0[2048 * 243];
__device__ float  g_buf1[2048 * 243];
__device__ float4 g_c4[243 * 2048];
__device__ int    g_mA[243 * 2048];

// ---- weight repack: dst[i][o][n] = sw[o][i][n], n padded to 105 ----
__global__ void repack_kernel(const float* __restrict__ sw, int wsel,
                              int in_f, int out_f)
{
    float* dst = (wsel == 0) ? g_wp0
                             : g_wpm + (size_t)(wsel - 1) * 243 * OPAD * WSD;
    int row = blockIdx.x;            // = i * out_f + o
    int i   = row / out_f;
    int o   = row - i * out_f;
    int n   = threadIdx.x;
    if (n < WSD) {
        float v = (n < NBASIS) ? sw[((size_t)o * in_f + i) * NBASIS + n] : 0.0f;
        dst[((size_t)i * OPAD + o) * WSD + n] = v;
    }
}

// ---- per-layer coefficient precompute: c4/mA at [i][b] ----
__global__ void coeff_kernel(const float* __restrict__ xin, int src_sel, int in_f)
{
    const float* hin = (src_sel == 0) ? xin : (src_sel == 1 ? g_buf0 : g_buf1);
    int i = blockIdx.x;
    int b = blockIdx.y * blockDim.x + threadIdx.x;

    float x  = hin[(size_t)b * in_f + i];
    float p  = (x + 0.5f) * 50.0f;            // (x - grid_interior0)/H, H = 0.02
    float mf = floorf(p);
    int   m  = (int)mf;
    float u  = p - mf;
    float u2 = u * u, u3 = u2 * u;
    float om = 1.0f - u;
    float c0 = om * om * om * (1.0f / 6.0f);
    float c1 = (3.0f * u3 - 6.0f * u2 + 4.0f) * (1.0f / 6.0f);
    float c2 = (-3.0f * u3 + 3.0f * u2 + 3.0f * u + 1.0f) * (1.0f / 6.0f);
    float c3 = u3 * (1.0f / 6.0f);
    if (m < -3 || m > 102) { c0 = c1 = c2 = c3 = 0.0f; m = 0; }
    else {
        if (m     < 0 || m     > 102) c0 = 0.0f;
        if (m + 1 < 0 || m + 1 > 102) c1 = 0.0f;
        if (m + 2 < 0 || m + 2 > 102) c2 = 0.0f;
        if (m + 3 < 0 || m + 3 > 102) c3 = 0.0f;
    }
    int n0 = min(max(m,     0), 102);
    int n1 = min(max(m + 1, 0), 102);
    int n2 = min(max(m + 2, 0), 102);
    int n3 = min(max(m + 3, 0), 102);

    g_c4[(size_t)i * 2048 + b] = make_float4(c0, c1, c2, c3);
    g_mA[(size_t)i * 2048 + b] = n0 | (n1 << 8) | (n2 << 16) | (n3 << 24);
}

// ---- main layer kernel: 128 batch x 32 outputs per CTA ----
__global__ void __launch_bounds__(LTH, 1)
kan_layer_kernel(const float* __restrict__ xin, float* __restrict__ dfinal,
                 int src_sel, int dst_sel, int wsel,
                 const float* __restrict__ bw,
                 const float* __restrict__ wbp, const float* __restrict__ wsp,
                 int in_f, int out_f, int residual)
{
    const float* hin  = (src_sel == 0) ? xin : (src_sel == 1 ? g_buf0 : g_buf1);
    float*       hout = (dst_sel == 1) ? g_buf0 : (dst_sel == 2 ? g_buf1 : dfinal);
    const float* wp   = (wsel == 0) ? g_wp0
                                    : g_wpm + (size_t)(wsel - 1) * 243 * OPAD * WSD;

    __shared__ __align__(16) float  slab[2 * BN * WSD];  // 2 x 13.4KB
    __shared__ float4 c4s[2 * BM];
    __shared__ int    mas[2 * BM];

    const int tid = threadIdx.x;
    const int b0  = blockIdx.x * BM;
    const int o0  = blockIdx.y * BN;
    const int ow  = min(BN, out_f - o0);
    const int w   = tid >> 5;
    const int l   = tid & 31;

    // Stage slab + coefficients for feature i into buffer `buf`.
    auto stage = [&](int i, int buf) {
        // (i*OPAD + o0) is a multiple of 32 -> *105 is a multiple of 4 floats
        const float4* src = (const float4*)(wp + ((size_t)i * OPAD + o0) * WSD);
        float4*       dst = (float4*)(slab + buf * (BN * WSD));
        for (int k = tid; k < (BN * WSD) / 4; k += LTH)   // 840 float4, <=2 iters
            dst[k] = src[k];
        if (tid < BM) {
            c4s[buf * BM + tid] = g_c4[(size_t)i * 2048 + b0 + tid];
            mas[buf * BM + tid] = g_mA[(size_t)i * 2048 + b0 + tid];
        }
    };

    float acc[8];
#pragma unroll
    for (int r = 0; r < 8; r++) acc[r] = 0.0f;

    const float* row0 = slab + l * WSD;   // lane -> output column (conflict-free)

    stage(0, 0);
    __syncthreads();

    for (int i = 0; i < in_f; i++) {
        const int cur = i & 1;
        if (i + 1 < in_f) stage(i + 1, cur ^ 1);

        const float*  row = row0 + cur * (BN * WSD);
        const float4* C   = c4s + cur * BM + w * 8;
        const int*    M   = mas + cur * BM + w * 8;
#pragma unroll
        for (int r = 0; r < 8; r++) {
            float4 c  = C[r];
            int    pk = M[r];
            float  a  = acc[r];
            a = fmaf(c.x, row[ pk        & 255], a);
            a = fmaf(c.y, row[(pk >> 8)  & 255], a);
            a = fmaf(c.z, row[(pk >> 16) & 255], a);
            a = fmaf(c.w, row[(pk >> 24) & 255], a);
            acc[r] = a;
        }
        __syncthreads();
    }

    const float wsv = wsp[0];
    const float wbv = wbp[0];

    // Base silu-GEMM path (dataset has wb == 0 -> normally skipped).
    float base[8];
#pragma unroll
    for (int r = 0; r < 8; r++) base[r] = 0.0f;
    if (wbv != 0.0f) {
        for (int i = 0; i < in_f; i++) {
            float bwv = (l < ow) ? bw[(size_t)(o0 + l) * in_f + i] : 0.0f;
#pragma unroll
            for (int r = 0; r < 8; r++) {
                float xv = hin[(size_t)(b0 + w * 8 + r) * in_f + i];
                float s  = xv / (1.0f + expf(-xv));
                base[r]  = fmaf(s, bwv, base[r]);
            }
        }
    }

    if (l < ow) {
#pragma unroll
        for (int r = 0; r < 8; r++) {
            int   b = b0 + w * 8 + r;
            float v = wsv * acc[r] + wbv * base[r];
            if (residual) v += hin[(size_t)b * in_f + o0 + l];
            hout[(size_t)b * out_f + o0 + l] = v;
        }
    }
}

// ---- final layer: 243 -> 1, one thread per batch row ----
__global__ void __launch_bounds__(256)
kan_last_kernel(int src_sel,
                const float* __restrict__ sw, const float* __restrict__ bw,
                const float* __restrict__ wbp, const float* __restrict__ wsp,
                float* __restrict__ out, int in_f)
{
    const float* hin = (src_sel == 1) ? g_buf0 : g_buf1;
    int b = blockIdx.x * blockDim.x + threadIdx.x;
    if (b >= 2048) return;

    const float wbv = wbp[0];
    float accS = 0.0f, accB = 0.0f;
    for (int i = 0; i < in_f; i++) {
        float x  = hin[(size_t)b * in_f + i];
        float p  = (x + 0.5f) * 50.0f;
        float mf = floorf(p);
        int   m  = (int)mf;
        float u  = p - mf;
        float u2 = u * u, u3 = u2 * u;
        float om = 1.0f - u;
        float c0 = om * om * om * (1.0f / 6.0f);
        float c1 = (3.0f * u3 - 6.0f * u2 + 4.0f) * (1.0f / 6.0f);
        float c2 = (-3.0f * u3 + 3.0f * u2 + 3.0f * u + 1.0f) * (1.0f / 6.0f);
        float c3 = u3 * (1.0f / 6.0f);
        if (m < -3 || m > 102) { c0 = c1 = c2 = c3 = 0.0f; m = 0; }
        else {
            if (m     < 0 || m     > 102) c0 = 0.0f;
            if (m + 1 < 0 || m + 1 > 102) c1 = 0.0f;
            if (m + 2 < 0 || m + 2 > 102) c2 = 0.0f;
            if (m + 3 < 0 || m + 3 > 102) c3 = 0.0f;
        }
        int n0 = min(max(m,     0), 102);
        int n1 = min(max(m + 1, 0), 102);
        int n2 = min(max(m + 2, 0), 102);
        int n3 = min(max(m + 3, 0), 102);
        const float* row = sw + (size_t)i * NBASIS;
        accS = fmaf(c0, row[n0], accS);
        accS = fmaf(c1, row[n1], accS);
        accS = fmaf(c2, row[n2], accS);
        accS = fmaf(c3, row[n3], accS);
        if (wbv != 0.0f) accB = fmaf(x / (1.0f + expf(-x)), bw[i], accB);
    }
    out[b] = wsp[0] * accS + wbv * accB;
}

extern "C" void kernel_launch(void* const* d_in, const int* in_sizes, int n_in,
                              void* d_out, int out_size)
{
    const float* x = (const float*)d_in[0];
    const float* bw[6]; const float* sw[6]; const float* wb[6]; const float* ws[6];
    for (int layer = 0; layer < 6; layer++) {
        bw[layer] = (const float*)d_in[1 + 4 * layer];
        sw[layer] = (const float*)d_in[2 + 4 * layer];
        wb[layer] = (const float*)d_in[3 + 4 * layer];
        ws[layer] = (const float*)d_in[4 + 4 * layer];
    }
    float* out = (float*)d_out;

    // Repack all spline weights (independent of activations).
    repack_kernel<<< 64 * 243, 128>>>(sw[0], 0,  64, 243);
    repack_kernel<<<243 * 243, 128>>>(sw[1], 1, 243, 243);
    repack_kernel<<<243 * 243, 128>>>(sw[2], 2, 243, 243);
    repack_kernel<<<243 * 243, 128>>>(sw[3], 3, 243, 243);
    repack_kernel<<<243 * 243, 128>>>(sw[4], 4, 243, 243);

    dim3 lgrid(2048 / BM, 243 / BN + ((243 % BN) ? 1 : 0));  // 16 x 8
    dim3 lblk(LTH);

    // Layer 0: x -> buf0
    coeff_kernel<<<dim3(64, 8), 256>>>(x, 0, 64);
    kan_layer_kernel<<<lgrid, lblk>>>(x, out, 0, 1, 0, bw[0], wb[0], ws[0], 64, 243, 0);
    // Layer 1: buf0 -> buf1
    coeff_kernel<<<dim3(243, 8), 256>>>(x, 1, 243);
    kan_layer_kernel<<<lgrid, lblk>>>(x, out, 1, 2, 1, bw[1], wb[1], ws[1], 243, 243, 1);
    // Layer 2: buf1 -> buf0
    coeff_kernel<<<dim3(243, 8), 256>>>(x, 2, 243);
    kan_layer_kernel<<<lgrid, lblk>>>(x, out, 2, 1, 2, bw[2], wb[2], ws[2], 243, 243, 1);
    // Layer 3: buf0 -> buf1
    coeff_kernel<<<dim3(243, 8), 256>>>(x, 1, 243);
    kan_layer_kernel<<<lgrid, lblk>>>(x, out, 1, 2, 3, bw[3], wb[3], ws[3], 243, 243, 1);
    // Layer 4: buf1 -> buf0
    coeff_kernel<<<dim3(243, 8), 256>>>(x, 2, 243);
    kan_layer_kernel<<<lgrid, lblk>>>(x, out, 2, 1, 4, bw[4], wb[4], ws[4], 243, 243, 1);
    // Layer 5: buf0 -> out
    kan_last_kernel<<<2048 / 256, 256>>>(1, sw[5], bw[5], wb[5], ws[5], out, 243);
}

// round 5
// speedup vs baseline: 2.5348x; 2.0617x over previous
#include <cuda_runtime.h>
#include <math.h>

// ---------------------------------------------------------------------------
// ResidualSieveKAN v4 — uniform-knot cubic B-spline KAN, fp32 everywhere.
//   y[b,o] = ws * sum_i sum_{t=0..3} c_t(b,i) * P_i,o[q(b,i)+t]   (+residual)
// P = weight row zero-padded (len 111): P[p]=w[p-3] for p in [3,106), else 0,
// so reference edge masking is automatic; q = m+3; fully-outside -> q=106
// (4 zero taps). Register-pipelined staging, barrier every 3 features,
// activations kept transposed [i][2048].
// ---------------------------------------------------------------------------

#define NB     103
#define RSF    111          // fp32 stride per o-row (111%32=15, odd -> conflict-free)
#define PADOFF 106          // tap base for fully-outside samples (all-zero taps)
#define OPAD   256
#define BM     128
#define BN     32
#define LTH    512
#define GI     3            // features per epoch (243 = 81*3)
#define SLAB_F   (BN * RSF)                    // 3552 floats per i-slab
#define SLAB_Q   (SLAB_F / 4)                  // 888 float4
#define SLAB_BYTES (2 * GI * SLAB_F * 4)       // 85248
#define SMEM_TOTAL (SLAB_BYTES + 2 * GI * BM * 16)   // + crec = 97536

__device__ float g_wp0[(size_t)64 * OPAD * RSF];
__device__ float g_wpm[(size_t)4 * 243 * OPAD * RSF];
__device__ float g_bufA[243 * 2048];
__device__ float g_bufB[243 * 2048];

// ---- repack: dst[i][o][p] = padded sw[o][i][p-3]; dummy o-rows stay zero ---
__global__ void repack_kernel(const float* __restrict__ s0, const float* __restrict__ s1,
                              const float* __restrict__ s2, const float* __restrict__ s3,
                              const float* __restrict__ s4)
{
    int wid  = blockIdx.x * (blockDim.x >> 5) + (threadIdx.x >> 5);
    int lane = threadIdx.x & 31;
    const int L0R  = 64 * OPAD;          // 16384 rows
    const int MIDR = 243 * OPAD;         // 62208 rows
    if (wid >= L0R + 4 * MIDR) return;

    const float* src;
    float* dst;
    int i, o, in_f;
    if (wid < L0R) {
        i = wid >> 8; o = wid & 255; in_f = 64;
        src = s0; dst = g_wp0 + (size_t)wid * RSF;
    } else {
        int rm = wid - L0R;
        int L  = rm / MIDR;
        int r2 = rm - L * MIDR;
        i = r2 >> 8; o = r2 & 255; in_f = 243;
        src = (L == 0) ? s1 : (L == 1) ? s2 : (L == 2) ? s3 : s4;
        dst = g_wpm + ((size_t)L * MIDR + r2) * RSF;
    }
    if (o >= 243) return;                 // dummy rows: zero-initialized bss
    const float* row = src + ((size_t)o * in_f + i) * NB;

#pragma unroll
    for (int k = 0; k < 4; k++) {
        int t = lane + 32 * k;
        if (t < RSF)
            dst[t] = (t >= 3 && t < 106) ? __ldg(row + t - 3) : 0.0f;
    }
}

// ---- transpose x [2048][64] -> bufA [64][2048] ----------------------------
__global__ void transpose_x_kernel(const float* __restrict__ x, float* __restrict__ dst)
{
    __shared__ float t[32][33];
    int bx = blockIdx.x, by = blockIdx.y;
    int tx = threadIdx.x, ty = threadIdx.y;
#pragma unroll
    for (int k = 0; k < 4; k++)
        t[ty + k * 8][tx] = x[(size_t)(bx * 32 + ty + k * 8) * 64 + by * 32 + tx];
    __syncthreads();
#pragma unroll
    for (int k = 0; k < 4; k++)
        dst[(size_t)(by * 32 + ty + k * 8) * 2048 + bx * 32 + tx] = t[tx][ty + k * 8];
}

// ---- main layer kernel: 128 batch x 32 outputs per CTA --------------------
__global__ void __launch_bounds__(LTH, 1)
kan_layer_kernel(const float* __restrict__ actin, float* __restrict__ actout,
                 const float* __restrict__ wp,
                 const float* __restrict__ bw,
                 const float* __restrict__ wbp, const float* __restrict__ wsp,
                 int in_f, int out_f, int residual)
{
    extern __shared__ __align__(16) unsigned char smem[];
    float*  slab = (float*)smem;                       // [2][GI][SLAB_F]
    float4* crec = (float4*)(smem + SLAB_BYTES);       // [2][GI][BM]

    const int tid = threadIdx.x;
    const int w   = tid >> 5;
    const int l   = tid & 31;
    const int b0  = blockIdx.x * BM;
    const int o0  = blockIdx.y * BN;
    const int nE  = (in_f + GI - 1) / GI;
    const int cb  = tid & 127;         // coeff: local b
    const int ci  = tid >> 7;          // coeff: i_local (valid for tid < 384)

    float acc[8];
#pragma unroll
    for (int r = 0; r < 8; r++) acc[r] = 0.0f;

    float4 stg[GI][2];
    float  xreg = 0.0f;

    // Phase 1: global loads for epoch e into registers.
    auto ldStage = [&](int e) {
#pragma unroll
        for (int s = 0; s < GI; s++) {
            int isrc = min(e * GI + s, in_f - 1);
            const float4* src = (const float4*)(wp + ((size_t)isrc * OPAD + o0) * RSF);
#pragma unroll
            for (int k = 0; k < 2; k++) {
                int idx = tid + k * LTH;
                if (idx < SLAB_Q) stg[s][k] = __ldg(src + idx);
            }
        }
        if (tid < GI * BM) {
            int isrc = min(e * GI + ci, in_f - 1);
            xreg = actin[(size_t)isrc * 2048 + b0 + cb];
        }
    };
    // Phase 3: store staged slab + coefficient records into smem buffer e&1.
    auto stStage = [&](int e) {
        int buf = e & 1;
        float4* dstb = (float4*)(slab + buf * (GI * SLAB_F));
#pragma unroll
        for (int s = 0; s < GI; s++) {
#pragma unroll
            for (int k = 0; k < 2; k++) {
                int idx = tid + k * LTH;
                if (idx < SLAB_Q) dstb[s * SLAB_Q + idx] = stg[s][k];
            }
        }
        if (tid < GI * BM) {
            int i = e * GI + ci;
            float4 rec;
            rec.x = rec.y = rec.z = 0.0f;
            rec.w = __int_as_float(PADOFF);            // all-zero taps
            if (i < in_f) {
                float x  = xreg;
                float p  = (x + 0.5f) * 50.0f;         // H = 0.02
                float mf = floorf(p);
                int   m  = (int)mf;
                float u  = p - mf;
                if (m >= -3 && m <= 102) {
                    float u2 = u * u, u3 = u2 * u, om = 1.0f - u;
                    rec.x = om * om * om * (1.0f / 6.0f);
                    rec.y = (3.0f * u3 - 6.0f * u2 + 4.0f) * (1.0f / 6.0f);
                    rec.z = (-3.0f * u3 + 3.0f * u2 + 3.0f * u + 1.0f) * (1.0f / 6.0f);
                    rec.w = __int_as_float(m + 3);     // q in [0,105]
                }
            }
            crec[buf * (GI * BM) + ci * BM + cb] = rec;
        }
    };

    ldStage(0);
    stStage(0);
    __syncthreads();

    for (int e = 0; e < nE; e++) {
        const int buf = e & 1;
        if (e + 1 < nE) ldStage(e + 1);

#pragma unroll
        for (int s = 0; s < GI; s++) {
            const float*  rowp = slab + (buf * GI + s) * SLAB_F + l * RSF;
            const float4* cr   = crec + (buf * GI + s) * BM + (w << 3);
#pragma unroll
            for (int r = 0; r < 8; r++) {
                float4 rec = cr[r];
                int off = __float_as_int(rec.w);
                float c3 = 1.0f - rec.x - rec.y - rec.z;   // partition of unity
                float a = acc[r];
                a = fmaf(rec.x, rowp[off],     a);
                a = fmaf(rec.y, rowp[off + 1], a);
                a = fmaf(rec.z, rowp[off + 2], a);
                a = fmaf(c3,    rowp[off + 3], a);
                acc[r] = a;
            }
        }

        if (e + 1 < nE) stStage(e + 1);
        __syncthreads();
    }

    const float wsv = wsp[0];
    const float wbv = wbp[0];

    if (wbv != 0.0f) {   // base silu-GEMM path (wb==0 in dataset -> skipped)
        float base[8];
#pragma unroll
        for (int r = 0; r < 8; r++) base[r] = 0.0f;
        for (int i = 0; i < in_f; i++) {
            float bwv = (o0 + l < out_f) ? bw[(size_t)(o0 + l) * in_f + i] : 0.0f;
#pragma unroll
            for (int r = 0; r < 8; r++) {
                float xv = actin[(size_t)i * 2048 + b0 + (w << 3) + r];
                float sv = xv / (1.0f + expf(-xv));
                base[r]  = fmaf(sv, bwv, base[r]);
            }
        }
#pragma unroll
        for (int r = 0; r < 8; r++) acc[r] = wsv * acc[r] + wbv * base[r];
    } else {
#pragma unroll
        for (int r = 0; r < 8; r++) acc[r] *= wsv;
    }

    // Epilogue: transpose via smem, coalesced writes to [o][2048].
    __syncthreads();
    float* trans = (float*)smem;                 // [32][129]
#pragma unroll
    for (int r = 0; r < 8; r++) trans[l * 129 + (w << 3) + r] = acc[r];
    __syncthreads();

    int o   = tid >> 4;                          // 0..31
    int c0b = (tid & 15) << 3;                   // 0..120
    if (o0 + o < out_f) {
        const float* tr  = trans + o * 129 + c0b;
        float*       dst = actout + (size_t)(o0 + o) * 2048 + b0 + c0b;
        const float* res = actin  + (size_t)(o0 + o) * 2048 + b0 + c0b;
#pragma unroll
        for (int k = 0; k < 8; k++) {
            float v = tr[k];
            if (residual) v += res[k];
            dst[k] = v;
        }
    }
}

// ---- final layer: 243 -> 1 (fp32 original weights, transposed act) --------
__global__ void __launch_bounds__(256)
kan_last_kernel(const float* __restrict__ hin,
                const float* __restrict__ sw, const float* __restrict__ bw,
                const float* __restrict__ wbp, const float* __restrict__ wsp,
                float* __restrict__ out, int in_f)
{
    int b = blockIdx.x * blockDim.x + threadIdx.x;
    if (b >= 2048) return;

    const float wbv = wbp[0];
    float accS = 0.0f, accB = 0.0f;
    for (int i = 0; i < in_f; i++) {
        float x  = hin[(size_t)i * 2048 + b];
        float p  = (x + 0.5f) * 50.0f;
        float mf = floorf(p);
        int   m  = (int)mf;
        float u  = p - mf;
        float u2 = u * u, u3 = u2 * u, om = 1.0f - u;
        float c0 = om * om * om * (1.0f / 6.0f);
        float c1 = (3.0f * u3 - 6.0f * u2 + 4.0f) * (1.0f / 6.0f);
        float c2 = (-3.0f * u3 + 3.0f * u2 + 3.0f * u + 1.0f) * (1.0f / 6.0f);
        float c3 = u3 * (1.0f / 6.0f);
        if (m < -3 || m > 102) { c0 = c1 = c2 = c3 = 0.0f; m = 0; }
        else {
            if (m     < 0 || m     > 102) c0 = 0.0f;
            if (m + 1 < 0 || m + 1 > 102) c1 = 0.0f;
            if (m + 2 < 0 || m + 2 > 102) c2 = 0.0f;
            if (m + 3 < 0 || m + 3 > 102) c3 = 0.0f;
        }
        int n0 = min(max(m,     0), 102);
        int n1 = min(max(m + 1, 0), 102);
        int n2 = min(max(m + 2, 0), 102);
        int n3 = min(max(m + 3, 0), 102);
        const float* row = sw + (size_t)i * NB;
        accS = fmaf(c0, row[n0], accS);
        accS = fmaf(c1, row[n1], accS);
        accS = fmaf(c2, row[n2], accS);
        accS = fmaf(c3, row[n3], accS);
        if (wbv != 0.0f) accB = fmaf(x / (1.0f + expf(-x)), bw[i], accB);
    }
    out[b] = wsp[0] * accS + wbv * accB;
}

extern "C" void kernel_launch(void* const* d_in, const int* in_sizes, int n_in,
                              void* d_out, int out_size)
{
    const float* x = (const float*)d_in[0];
    const float* bw[6]; const float* sw[6]; const float* wb[6]; const float* ws[6];
    for (int layer = 0; layer < 6; layer++) {
        bw[layer] = (const float*)d_in[1 + 4 * layer];
        sw[layer] = (const float*)d_in[2 + 4 * layer];
        wb[layer] = (const float*)d_in[3 + 4 * layer];
        ws[layer] = (const float*)d_in[4 + 4 * layer];
    }
    float* out = (float*)d_out;

    void *pwp0, *pwpm, *pA, *pB;
    cudaGetSymbolAddress(&pwp0, g_wp0);
    cudaGetSymbolAddress(&pwpm, g_wpm);
    cudaGetSymbolAddress(&pA, g_bufA);
    cudaGetSymbolAddress(&pB, g_bufB);
    const float* wp0 = (const float*)pwp0;
    const float* wpm = (const float*)pwpm;
    float* A = (float*)pA;
    float* B = (float*)pB;
    const size_t MIDW = (size_t)243 * OPAD * RSF;

    cudaFuncSetAttribute(kan_layer_kernel,
                         cudaFuncAttributeMaxDynamicSharedMemorySize, SMEM_TOTAL);

    // 1) repack 265216 rows (8 warps/block)
    repack_kernel<<<33152, 256>>>(sw[0], sw[1], sw[2], sw[3], sw[4]);
    // 2) transpose x into A
    transpose_x_kernel<<<dim3(64, 2), dim3(32, 8)>>>(x, A);

    dim3 lgrid(2048 / BM, (243 + BN - 1) / BN);   // 16 x 8 = 128 CTAs
    // 3..7) layers (ncu -s 5 captures a mid layer)
    kan_layer_kernel<<<lgrid, LTH, SMEM_TOTAL>>>(A, B, wp0,            bw[0], wb[0], ws[0],  64, 243, 0);
    kan_layer_kernel<<<lgrid, LTH, SMEM_TOTAL>>>(B, A, wpm + 0 * MIDW, bw[1], wb[1], ws[1], 243, 243, 1);
    kan_layer_kernel<<<lgrid, LTH, SMEM_TOTAL>>>(A, B, wpm + 1 * MIDW, bw[2], wb[2], ws[2], 243, 243, 1);
    kan_layer_kernel<<<lgrid, LTH, SMEM_TOTAL>>>(B, A, wpm + 2 * MIDW, bw[3], wb[3], ws[3], 243, 243, 1);
    kan_layer_kernel<<<lgrid, LTH, SMEM_TOTAL>>>(A, B, wpm + 3 * MIDW, bw[4], wb[4], ws[4], 243, 243, 1);
    // 8) final layer
    kan_last_kernel<<<2048 / 256, 256>>>(B, sw[5], bw[5], wb[5], ws[5], out, 243);
}

// round 6
// speedup vs baseline: 3.1038x; 1.2245x over previous
#include <cuda_runtime.h>
#include <math.h>

// ---------------------------------------------------------------------------
// ResidualSieveKAN v5 — fp32, uniform-knot cubic B-spline.
//   y[b,o] = ws * sum_i sum_t c_t(b,i) * P_i,o[q(b,i)+t]   (+residual)
// v5: BM=64 / 256 threads / grid 32x8 -> 2 CTAs per SM (latency hiding);
// slab staging via cp.async.cg (L1-bypass, zero staging registers),
// double-buffered groups; coeff x-loads register-pipelined one epoch ahead.
// ---------------------------------------------------------------------------

#define NB     103
#define RSF    111          // fp32 row stride (odd -> conflict-free LDS)
#define PADOFF 106          // tap base for fully-outside samples (zero taps)
#define OPAD   256
#define BM     64
#define BN     32
#define LTH    256
#define GI     3            // features per epoch (243 = 81*3)
#define SLAB_F   (BN * RSF)                  // 3552 floats per i-slab
#define SLAB_Q   (SLAB_F / 4)                // 888 float4
#define SLAB_BYTES (2 * GI * SLAB_F * 4)     // 85248
#define CREC_BYTES (2 * GI * BM * 16)        // 6144
#define SMEM_TOTAL (SLAB_BYTES + CREC_BYTES) // 91392 -> 2 CTAs/SM

__device__ float g_wp0[(size_t)64 * OPAD * RSF];
__device__ float g_wpm[(size_t)4 * 243 * OPAD * RSF];
__device__ float g_bufA[243 * 2048];
__device__ float g_bufB[243 * 2048];

__device__ __forceinline__ void cp16(unsigned int dst, const void* src) {
    asm volatile("cp.async.cg.shared.global [%0], [%1], 16;\n"
                 :: "r"(dst), "l"(src));
}
__device__ __forceinline__ void cp_commit() {
    asm volatile("cp.async.commit_group;\n" ::: "memory");
}
__device__ __forceinline__ void cp_wait1() {
    asm volatile("cp.async.wait_group 1;\n" ::: "memory");
}
__device__ __forceinline__ void cp_wait0() {
    asm volatile("cp.async.wait_group 0;\n" ::: "memory");
}

// ---- repack: dst[i][o][p] = padded sw[o][i][p-3]; dummy o-rows stay zero ---
__global__ void repack_kernel(const float* __restrict__ s0, const float* __restrict__ s1,
                              const float* __restrict__ s2, const float* __restrict__ s3,
                              const float* __restrict__ s4)
{
    int wid  = blockIdx.x * (blockDim.x >> 5) + (threadIdx.x >> 5);
    int lane = threadIdx.x & 31;
    const int L0R  = 64 * OPAD;
    const int MIDR = 243 * OPAD;
    if (wid >= L0R + 4 * MIDR) return;

    const float* src;
    float* dst;
    int i, o, in_f;
    if (wid < L0R) {
        i = wid >> 8; o = wid & 255; in_f = 64;
        src = s0; dst = g_wp0 + (size_t)wid * RSF;
    } else {
        int rm = wid - L0R;
        int L  = rm / MIDR;
        int r2 = rm - L * MIDR;
        i = r2 >> 8; o = r2 & 255; in_f = 243;
        src = (L == 0) ? s1 : (L == 1) ? s2 : (L == 2) ? s3 : s4;
        dst = g_wpm + ((size_t)L * MIDR + r2) * RSF;
    }
    if (o >= 243) return;                 // dummy rows stay zero (bss)
    const float* row = src + ((size_t)o * in_f + i) * NB;

#pragma unroll
    for (int k = 0; k < 4; k++) {
        int t = lane + 32 * k;
        if (t < RSF)
            dst[t] = (t >= 3 && t < 106) ? __ldg(row + t - 3) : 0.0f;
    }
}

// ---- transpose x [2048][64] -> bufA [64][2048] ----------------------------
__global__ void transpose_x_kernel(const float* __restrict__ x, float* __restrict__ dst)
{
    __shared__ float t[32][33];
    int bx = blockIdx.x, by = blockIdx.y;
    int tx = threadIdx.x, ty = threadIdx.y;
#pragma unroll
    for (int k = 0; k < 4; k++)
        t[ty + k * 8][tx] = x[(size_t)(bx * 32 + ty + k * 8) * 64 + by * 32 + tx];
    __syncthreads();
#pragma unroll
    for (int k = 0; k < 4; k++)
        dst[(size_t)(by * 32 + ty + k * 8) * 2048 + bx * 32 + tx] = t[tx][ty + k * 8];
}

// ---- main layer kernel: 64 batch x 32 outputs per CTA, 2 CTAs/SM ----------
__global__ void __launch_bounds__(LTH, 2)
kan_layer_kernel(const float* __restrict__ actin, float* __restrict__ actout,
                 const float* __restrict__ wp,
                 const float* __restrict__ bw,
                 const float* __restrict__ wbp, const float* __restrict__ wsp,
                 int in_f, int out_f, int residual)
{
    extern __shared__ __align__(16) unsigned char smem[];
    float*  slab = (float*)smem;                       // [2][GI][SLAB_F]
    float4* crec = (float4*)(smem + SLAB_BYTES);       // [2][GI][BM]
    const unsigned int slabAddr = (unsigned int)__cvta_generic_to_shared(slab);

    const int tid = threadIdx.x;
    const int w   = tid >> 5;          // 0..7, handles rows w*8..w*8+7
    const int l   = tid & 31;          // lane -> output column
    const int b0  = blockIdx.x * BM;
    const int o0  = blockIdx.y * BN;
    const int nE  = (in_f + GI - 1) / GI;
    const int cb  = tid & (BM - 1);    // coeff: local b
    const int ci  = tid >> 6;          // coeff: i_local (valid for tid < 192)

    float acc[8];
#pragma unroll
    for (int r = 0; r < 8; r++) acc[r] = 0.0f;

    // ---- issue one epoch's slabs via cp.async into buffer e&1 ----
    auto issueEpoch = [&](int e) {
        if (e >= nE) return;
        int buf = e & 1;
#pragma unroll
        for (int s = 0; s < GI; s++) {
            int isrc = min(e * GI + s, in_f - 1);
            const float* src = wp + ((size_t)isrc * OPAD + o0) * RSF;
            unsigned int dst = slabAddr + (unsigned int)((buf * GI + s) * SLAB_F) * 4u;
#pragma unroll
            for (int k = 0; k < 4; k++) {
                int idx = tid + k * LTH;
                if (idx < SLAB_Q) cp16(dst + idx * 16u, src + idx * 4);
            }
        }
    };

    // ---- coefficient record from x value ----
    auto makeRec = [&](float x, int valid) -> float4 {
        float4 rec;
        rec.x = rec.y = rec.z = 0.0f;
        rec.w = __int_as_float(PADOFF);
        if (valid) {
            float p  = (x + 0.5f) * 50.0f;          // H = 0.02
            float mf = floorf(p);
            int   m  = (int)mf;
            float u  = p - mf;
            if (m >= -3 && m <= 102) {
                float u2 = u * u, u3 = u2 * u, om = 1.0f - u;
                rec.x = om * om * om * (1.0f / 6.0f);
                rec.y = (3.0f * u3 - 6.0f * u2 + 4.0f) * (1.0f / 6.0f);
                rec.z = (-3.0f * u3 + 3.0f * u2 + 3.0f * u + 1.0f) * (1.0f / 6.0f);
                rec.w = __int_as_float(m + 3);      // q in [0,105]
            }
        }
        return rec;
    };

    const bool cth = (tid < GI * BM);
    float xreg = 0.0f;

    // ---- prologue: epochs 0,1 in flight; crec(0) stored; x(1) in xreg ----
    issueEpoch(0); cp_commit();
    issueEpoch(1); cp_commit();
    if (cth) {
        float x0 = actin[(size_t)min(ci, in_f - 1) * 2048 + b0 + cb];
        crec[ci * BM + cb] = makeRec(x0, ci < in_f);
        if (nE > 1) {
            int i1 = min(GI + ci, in_f - 1);
            xreg = actin[(size_t)i1 * 2048 + b0 + cb];
        }
    }

    for (int e = 0; e < nE; e++) {
        const int buf = e & 1;
        cp_wait1();                // epoch e slabs resident (<=1 group pending)
        __syncthreads();           // slabs + crec(e) visible to all warps

#pragma unroll
        for (int s = 0; s < GI; s++) {
            const float*  rowp = slab + (buf * GI + s) * SLAB_F + l * RSF;
            const float4* cr   = crec + (buf * GI + s) * BM + (w << 3);
#pragma unroll
            for (int r = 0; r < 8; r++) {
                float4 rec = cr[r];
                int off = __float_as_int(rec.w);
                float c3 = 1.0f - rec.x - rec.y - rec.z;   // partition of unity
                float a = acc[r];
                a = fmaf(rec.x, rowp[off],     a);
                a = fmaf(rec.y, rowp[off + 1], a);
                a = fmaf(rec.z, rowp[off + 2], a);
                a = fmaf(c3,    rowp[off + 3], a);
                acc[r] = a;
            }
        }
        __syncthreads();           // everyone done reading buf before overwrite

        issueEpoch(e + 2);         // into buf (e&1); may be empty at tail
        cp_commit();               // always commit -> constant group count
        if (cth) {
            if (e + 1 < nE) {      // crec(e+1) from xreg (loaded last iter)
                int i1 = (e + 1) * GI + ci;
                crec[((e + 1) & 1) * (GI * BM) + ci * BM + cb] =
                    makeRec(xreg, i1 < in_f);
            }
            if (e + 2 < nE) {      // prefetch x(e+2)
                int i2 = min((e + 2) * GI + ci, in_f - 1);
                xreg = actin[(size_t)i2 * 2048 + b0 + cb];
            }
        }
    }
    cp_wait0();                    // drain before smem reuse

    const float wsv = wsp[0];
    const float wbv = wbp[0];

    if (wbv != 0.0f) {   // base silu-GEMM path (wb==0 in dataset -> skipped)
        float base[8];
#pragma unroll
        for (int r = 0; r < 8; r++) base[r] = 0.0f;
        for (int i = 0; i < in_f; i++) {
            float bwv = (o0 + l < out_f) ? bw[(size_t)(o0 + l) * in_f + i] : 0.0f;
#pragma unroll
            for (int r = 0; r < 8; r++) {
                float xv = actin[(size_t)i * 2048 + b0 + (w << 3) + r];
                float sv = xv / (1.0f + expf(-xv));
                base[r]  = fmaf(sv, bwv, base[r]);
            }
        }
#pragma unroll
        for (int r = 0; r < 8; r++) acc[r] = wsv * acc[r] + wbv * base[r];
    } else {
#pragma unroll
        for (int r = 0; r < 8; r++) acc[r] *= wsv;
    }

    // ---- epilogue: transpose via smem, coalesced writes to [o][2048] ----
    __syncthreads();
    float* trans = (float*)smem;                 // [32][65]
#pragma unroll
    for (int r = 0; r < 8; r++) trans[l * 65 + (w << 3) + r] = acc[r];
    __syncthreads();

    int o    = tid >> 3;                         // 0..31
    int bloc = (tid & 7) << 3;                   // 0..56
    if (o0 + o < out_f) {
        const float* tr  = trans + o * 65 + bloc;
        float*       dst = actout + (size_t)(o0 + o) * 2048 + b0 + bloc;
        const float* res = actin  + (size_t)(o0 + o) * 2048 + b0 + bloc;
#pragma unroll
        for (int k = 0; k < 8; k++) {
            float v = tr[k];
            if (residual) v += res[k];
            dst[k] = v;
        }
    }
}

// ---- final layer: 243 -> 1 (fp32 original weights, transposed act) --------
__global__ void __launch_bounds__(256)
kan_last_kernel(const float* __restrict__ hin,
                const float* __restrict__ sw, const float* __restrict__ bw,
                const float* __restrict__ wbp, const float* __restrict__ wsp,
                float* __restrict__ out, int in_f)
{
    int b = blockIdx.x * blockDim.x + threadIdx.x;
    if (b >= 2048) return;

    const float wbv = wbp[0];
    float accS = 0.0f, accB = 0.0f;
    for (int i = 0; i < in_f; i++) {
        float x  = hin[(size_t)i * 2048 + b];
        float p  = (x + 0.5f) * 50.0f;
        float mf = floorf(p);
        int   m  = (int)mf;
        float u  = p - mf;
        float u2 = u * u, u3 = u2 * u, om = 1.0f - u;
        float c0 = om * om * om * (1.0f / 6.0f);
        float c1 = (3.0f * u3 - 6.0f * u2 + 4.0f) * (1.0f / 6.0f);
        float c2 = (-3.0f * u3 + 3.0f * u2 + 3.0f * u + 1.0f) * (1.0f / 6.0f);
        float c3 = u3 * (1.0f / 6.0f);
        if (m < -3 || m > 102) { c0 = c1 = c2 = c3 = 0.0f; m = 0; }
        else {
            if (m     < 0 || m     > 102) c0 = 0.0f;
            if (m + 1 < 0 || m + 1 > 102) c1 = 0.0f;
            if (m + 2 < 0 || m + 2 > 102) c2 = 0.0f;
            if (m + 3 < 0 || m + 3 > 102) c3 = 0.0f;
        }
        int n0 = min(max(m,     0), 102);
        int n1 = min(max(m + 1, 0), 102);
        int n2 = min(max(m + 2, 0), 102);
        int n3 = min(max(m + 3, 0), 102);
        const float* row = sw + (size_t)i * NB;
        accS = fmaf(c0, row[n0], accS);
        accS = fmaf(c1, row[n1], accS);
        accS = fmaf(c2, row[n2], accS);
        accS = fmaf(c3, row[n3], accS);
        if (wbv != 0.0f) accB = fmaf(x / (1.0f + expf(-x)), bw[i], accB);
    }
    out[b] = wsp[0] * accS + wbv * accB;
}

extern "C" void kernel_launch(void* const* d_in, const int* in_sizes, int n_in,
                              void* d_out, int out_size)
{
    const float* x = (const float*)d_in[0];
    const float* bw[6]; const float* sw[6]; const float* wb[6]; const float* ws[6];
    for (int layer = 0; layer < 6; layer++) {
        bw[layer] = (const float*)d_in[1 + 4 * layer];
        sw[layer] = (const float*)d_in[2 + 4 * layer];
        wb[layer] = (const float*)d_in[3 + 4 * layer];
        ws[layer] = (const float*)d_in[4 + 4 * layer];
    }
    float* out = (float*)d_out;

    void *pwp0, *pwpm, *pA, *pB;
    cudaGetSymbolAddress(&pwp0, g_wp0);
    cudaGetSymbolAddress(&pwpm, g_wpm);
    cudaGetSymbolAddress(&pA, g_bufA);
    cudaGetSymbolAddress(&pB, g_bufB);
    const float* wp0 = (const float*)pwp0;
    const float* wpm = (const float*)pwpm;
    float* A = (float*)pA;
    float* B = (float*)pB;
    const size_t MIDW = (size_t)243 * OPAD * RSF;

    cudaFuncSetAttribute(kan_layer_kernel,
                         cudaFuncAttributeMaxDynamicSharedMemorySize, SMEM_TOTAL);

    // 1) repack 265216 rows (8 warps/block)
    repack_kernel<<<33152, 256>>>(sw[0], sw[1], sw[2], sw[3], sw[4]);
    // 2) transpose x into A
    transpose_x_kernel<<<dim3(64, 2), dim3(32, 8)>>>(x, A);

    dim3 lgrid(2048 / BM, (243 + BN - 1) / BN);   // 32 x 8 = 256 CTAs
    // 3..7) layers
    kan_layer_kernel<<<lgrid, LTH, SMEM_TOTAL>>>(A, B, wp0,            bw[0], wb[0], ws[0],  64, 243, 0);
    kan_layer_kernel<<<lgrid, LTH, SMEM_TOTAL>>>(B, A, wpm + 0 * MIDW, bw[1], wb[1], ws[1], 243, 243, 1);
    kan_layer_kernel<<<lgrid, LTH, SMEM_TOTAL>>>(A, B, wpm + 1 * MIDW, bw[2], wb[2], ws[2], 243, 243, 1);
    kan_layer_kernel<<<lgrid, LTH, SMEM_TOTAL>>>(B, A, wpm + 2 * MIDW, bw[3], wb[3], ws[3], 243, 243, 1);
    kan_layer_kernel<<<lgrid, LTH, SMEM_TOTAL>>>(A, B, wpm + 3 * MIDW, bw[4], wb[4], ws[4], 243, 243, 1);
    // 8) final layer
    kan_last_kernel<<<2048 / 256, 256>>>(B, sw[5], bw[5], wb[5], ws[5], out, 243);
}